// round 1
// baseline (speedup 1.0000x reference)
#include <cuda_runtime.h>
#include <math_constants.h>

#define T_TOK    512
#define NHEADS   64
#define DQK      576
#define DVDIM    512
#define TOPKN    512
#define HG       32
#define KC       64
#define KSTRIDE  577   // 577 % 32 == 1 -> conflict-free row access
#define PSTRIDE  67    // 67 % 32 == 3  -> conflict-free column access
#define NTHREADS 256
#define ATTN_SCALE 0.04166666666666666f  // 576^-0.5 == 1/24

// shared memory layout (float offsets)
#define QS_OFF 0
#define QS_SZ  (HG * KSTRIDE)               // 18464
#define KS_OFF (QS_OFF + QS_SZ)
#define KS_SZ  (KC * KSTRIDE)               // 36928
#define PS_OFF (KS_OFF + KS_SZ)
#define PS_SZ  (HG * PSTRIDE)               // 2144
#define MS_OFF (PS_OFF + PS_SZ)
#define LS_OFF (MS_OFF + HG)
#define CS_OFF (LS_OFF + HG)
#define SM_TOTAL (CS_OFF + HG)              // 57632 floats = 230528 bytes

__global__ __launch_bounds__(NTHREADS, 1)
void mla_sparse_attn_kernel(const float* __restrict__ q,
                            const float* __restrict__ kv,
                            const int*   __restrict__ topk,
                            const float* __restrict__ sink,
                            float*       __restrict__ out)
{
    extern __shared__ float sm[];
    const int tid  = threadIdx.x;
    const int t    = blockIdx.y;
    const int hblk = blockIdx.x * HG;

    const float NEG_INF = -CUDART_INF_F;

    // ---- load Q tile (HG x 576) into smem ----
    {
        const float* qg = q + ((size_t)t * NHEADS + hblk) * DQK;
        for (int i = tid; i < HG * (DQK / 4); i += NTHREADS) {
            int row = i / (DQK / 4);
            int c4  = i % (DQK / 4);
            float4 v = *reinterpret_cast<const float4*>(qg + (size_t)row * DQK + c4 * 4);
            float* dst = &sm[QS_OFF + row * KSTRIDE + c4 * 4];
            dst[0] = v.x; dst[1] = v.y; dst[2] = v.z; dst[3] = v.w;
        }
    }
    if (tid < HG) {
        sm[MS_OFF + tid] = NEG_INF;
        sm[LS_OFF + tid] = 0.f;
    }

    // PV mapping: warp w owns heads {w, w+8, w+16, w+24}; lane c owns dv = c + 32*k
    const int w = tid >> 5;
    const int c = tid & 31;
    float acc[4][16];
    #pragma unroll
    for (int i = 0; i < 4; i++)
        #pragma unroll
        for (int k2 = 0; k2 < 16; k2++)
            acc[i][k2] = 0.f;

    const int* idxg = topk + (size_t)t * TOPKN;

    for (int ci = 0; ci < TOPKN / KC; ci++) {
        __syncthreads();  // previous PV done before k_s/p_s overwrite; also covers init

        // ---- gather K chunk (64 rows x 576) into smem ----
        for (int i = tid; i < KC * (DQK / 4); i += NTHREADS) {
            int row = i / (DQK / 4);
            int c4  = i % (DQK / 4);
            int gi  = __ldg(idxg + ci * KC + row);
            float4 v;
            if (gi >= 0)
                v = *reinterpret_cast<const float4*>(kv + (size_t)gi * DQK + c4 * 4);
            else
                v = make_float4(0.f, 0.f, 0.f, 0.f);
            float* dst = &sm[KS_OFF + row * KSTRIDE + c4 * 4];
            dst[0] = v.x; dst[1] = v.y; dst[2] = v.z; dst[3] = v.w;
        }
        __syncthreads();

        // ---- QK: scores S[32][64], 2h x 4j register tile per thread ----
        {
            const int ty = tid >> 4, tx = tid & 15;
            const float* q0 = &sm[QS_OFF + ty * KSTRIDE];
            const float* q1 = &sm[QS_OFF + (ty + 16) * KSTRIDE];
            const float* k0 = &sm[KS_OFF + tx * KSTRIDE];
            const float* k1 = &sm[KS_OFF + (tx + 16) * KSTRIDE];
            const float* k2p = &sm[KS_OFF + (tx + 32) * KSTRIDE];
            const float* k3 = &sm[KS_OFF + (tx + 48) * KSTRIDE];
            float s00 = 0.f, s01 = 0.f, s02 = 0.f, s03 = 0.f;
            float s10 = 0.f, s11 = 0.f, s12 = 0.f, s13 = 0.f;
            #pragma unroll 4
            for (int d = 0; d < DQK; d++) {
                float qa = q0[d], qb = q1[d];
                float ka = k0[d], kb = k1[d], kc2 = k2p[d], kd = k3[d];
                s00 += qa * ka;  s01 += qa * kb;  s02 += qa * kc2;  s03 += qa * kd;
                s10 += qb * ka;  s11 += qb * kb;  s12 += qb * kc2;  s13 += qb * kd;
            }
            float sva[4] = {s00, s01, s02, s03};
            float svb[4] = {s10, s11, s12, s13};
            #pragma unroll
            for (int m = 0; m < 4; m++) {
                int j  = tx + 16 * m;
                int gi = __ldg(idxg + ci * KC + j);
                float a = sva[m] * ATTN_SCALE;
                float b = svb[m] * ATTN_SCALE;
                if (gi < 0) { a = NEG_INF; b = NEG_INF; }
                sm[PS_OFF + ty * PSTRIDE + j]        = a;
                sm[PS_OFF + (ty + 16) * PSTRIDE + j] = b;
            }
        }
        __syncthreads();

        // ---- online softmax row update (one thread per head) ----
        if (tid < HG) {
            const int h = tid;
            float* prow = &sm[PS_OFF + h * PSTRIDE];
            float mc = NEG_INF;
            #pragma unroll 8
            for (int j = 0; j < KC; j++) mc = fmaxf(mc, prow[j]);
            float mp = sm[MS_OFF + h];
            float mn = fmaxf(mp, mc);
            float corr = (mp == NEG_INF) ? 0.f : __expf(mp - mn);
            float ssum = 0.f;
            #pragma unroll 8
            for (int j = 0; j < KC; j++) {
                float v = prow[j];
                float p = (v == NEG_INF) ? 0.f : __expf(v - mn);
                prow[j] = p;
                ssum += p;
            }
            sm[LS_OFF + h] = sm[LS_OFF + h] * corr + ssum;
            sm[MS_OFF + h] = mn;
            sm[CS_OFF + h] = corr;
        }
        __syncthreads();

        // ---- PV: acc = acc*corr + P_chunk @ V_chunk ----
        {
            float cr[4];
            #pragma unroll
            for (int i = 0; i < 4; i++) cr[i] = sm[CS_OFF + w + 8 * i];
            #pragma unroll
            for (int i = 0; i < 4; i++)
                #pragma unroll
                for (int k2 = 0; k2 < 16; k2++)
                    acc[i][k2] *= cr[i];

            #pragma unroll 2
            for (int j = 0; j < KC; j++) {
                float p0 = sm[PS_OFF + (w     ) * PSTRIDE + j];
                float p1 = sm[PS_OFF + (w +  8) * PSTRIDE + j];
                float p2 = sm[PS_OFF + (w + 16) * PSTRIDE + j];
                float p3 = sm[PS_OFF + (w + 24) * PSTRIDE + j];
                const float* vr = &sm[KS_OFF + j * KSTRIDE + c];
                #pragma unroll
                for (int k2 = 0; k2 < 16; k2++) {
                    float vv = vr[32 * k2];
                    acc[0][k2] += p0 * vv;
                    acc[1][k2] += p1 * vv;
                    acc[2][k2] += p2 * vv;
                    acc[3][k2] += p3 * vv;
                }
            }
        }
    }

    // ---- finalize: fold in sink, normalize, write out ----
    #pragma unroll
    for (int i = 0; i < 4; i++) {
        int h  = w + 8 * i;
        int gh = hblk + h;
        float m  = sm[MS_OFF + h];
        float l  = sm[LS_OFF + h];
        float sk = __ldg(sink + gh);
        float M  = fmaxf(m, sk);
        float cf = (m == NEG_INF) ? 0.f : __expf(m - M);
        float denom = l * cf + __expf(sk - M);
        float scl = cf / denom;
        float* og = out + ((size_t)t * NHEADS + gh) * DVDIM;
        #pragma unroll
        for (int k2 = 0; k2 < 16; k2++)
            og[c + 32 * k2] = acc[i][k2] * scl;
    }
}

extern "C" void kernel_launch(void* const* d_in, const int* in_sizes, int n_in,
                              void* d_out, int out_size)
{
    const float* q    = (const float*)d_in[0];
    const float* kv   = (const float*)d_in[1];
    const int*   topk = (const int*)d_in[2];
    const float* sink = (const float*)d_in[3];
    float* out = (float*)d_out;

    const size_t smem_bytes = SM_TOTAL * sizeof(float);  // 230528
    cudaFuncSetAttribute(mla_sparse_attn_kernel,
                         cudaFuncAttributeMaxDynamicSharedMemorySize,
                         (int)smem_bytes);
    dim3 grid(NHEADS / HG, T_TOK);
    mla_sparse_attn_kernel<<<grid, NTHREADS, smem_bytes>>>(q, kv, topk, sink, out);
}

// round 2
// speedup vs baseline: 1.0484x; 1.0484x over previous
#include <cuda_runtime.h>
#include <math_constants.h>

#define T_TOK    512
#define NHEADS   64
#define DQK      576
#define DVDIM    512
#define TOPKN    512
#define HG       32
#define KC       64
#define KSTRIDE  577   // 577 % 32 == 1 -> conflict-free row access
#define PSTRIDE  67    // 67 % 32 == 3  -> conflict-free column access
#define NTHREADS 256
#define ATTN_SCALE 0.04166666666666666f  // 576^-0.5 == 1/24

// shared memory layout (float offsets)
#define QS_OFF 0
#define QS_SZ  (HG * KSTRIDE)               // 18464
#define KS_OFF (QS_OFF + QS_SZ)
#define KS_SZ  (KC * KSTRIDE)               // 36928
#define PS_OFF (KS_OFF + KS_SZ)
#define PS_SZ  (HG * PSTRIDE)               // 2144
#define MS_OFF (PS_OFF + PS_SZ)
#define LS_OFF (MS_OFF + HG)
#define CS_OFF (LS_OFF + HG)
#define SM_TOTAL (CS_OFF + HG)              // 57632 floats = 230528 bytes

__global__ __launch_bounds__(NTHREADS, 1)
void mla_sparse_attn_kernel(const float* __restrict__ q,
                            const float* __restrict__ kv,
                            const int*   __restrict__ topk,
                            const float* __restrict__ sink,
                            float*       __restrict__ out)
{
    extern __shared__ float sm[];
    const int tid  = threadIdx.x;
    const int t    = blockIdx.y;
    const int hblk = blockIdx.x * HG;

    const float NEG_INF = -CUDART_INF_F;

    // ---- load Q tile (HG x 576) into smem ----
    {
        const float* qg = q + ((size_t)t * NHEADS + hblk) * DQK;
        for (int i = tid; i < HG * (DQK / 4); i += NTHREADS) {
            int row = i / (DQK / 4);
            int c4  = i % (DQK / 4);
            float4 v = *reinterpret_cast<const float4*>(qg + (size_t)row * DQK + c4 * 4);
            float* dst = &sm[QS_OFF + row * KSTRIDE + c4 * 4];
            dst[0] = v.x; dst[1] = v.y; dst[2] = v.z; dst[3] = v.w;
        }
    }
    if (tid < HG) {
        sm[MS_OFF + tid] = NEG_INF;
        sm[LS_OFF + tid] = 0.f;
    }

    // PV mapping: warp w owns heads {w, w+8, w+16, w+24}; lane c owns dv = c + 32*k
    const int w = tid >> 5;
    const int c = tid & 31;
    float acc[4][16];
    #pragma unroll
    for (int i = 0; i < 4; i++)
        #pragma unroll
        for (int k2 = 0; k2 < 16; k2++)
            acc[i][k2] = 0.f;

    const int* idxg = topk + (size_t)t * TOPKN;

    for (int ci = 0; ci < TOPKN / KC; ci++) {
        __syncthreads();  // previous PV done before k_s/p_s overwrite; also covers init

        // ---- gather K chunk (64 rows x 576) into smem ----
        for (int i = tid; i < KC * (DQK / 4); i += NTHREADS) {
            int row = i / (DQK / 4);
            int c4  = i % (DQK / 4);
            int gi  = __ldg(idxg + ci * KC + row);
            float4 v;
            if (gi >= 0)
                v = *reinterpret_cast<const float4*>(kv + (size_t)gi * DQK + c4 * 4);
            else
                v = make_float4(0.f, 0.f, 0.f, 0.f);
            float* dst = &sm[KS_OFF + row * KSTRIDE + c4 * 4];
            dst[0] = v.x; dst[1] = v.y; dst[2] = v.z; dst[3] = v.w;
        }
        __syncthreads();

        // ---- QK: scores S[32][64], 2h x 4j register tile per thread ----
        {
            const int ty = tid >> 4, tx = tid & 15;
            const float* q0 = &sm[QS_OFF + ty * KSTRIDE];
            const float* q1 = &sm[QS_OFF + (ty + 16) * KSTRIDE];
            const float* k0 = &sm[KS_OFF + tx * KSTRIDE];
            const float* k1 = &sm[KS_OFF + (tx + 16) * KSTRIDE];
            const float* k2p = &sm[KS_OFF + (tx + 32) * KSTRIDE];
            const float* k3 = &sm[KS_OFF + (tx + 48) * KSTRIDE];
            float s00 = 0.f, s01 = 0.f, s02 = 0.f, s03 = 0.f;
            float s10 = 0.f, s11 = 0.f, s12 = 0.f, s13 = 0.f;
            #pragma unroll 4
            for (int d = 0; d < DQK; d++) {
                float qa = q0[d], qb = q1[d];
                float ka = k0[d], kb = k1[d], kc2 = k2p[d], kd = k3[d];
                s00 += qa * ka;  s01 += qa * kb;  s02 += qa * kc2;  s03 += qa * kd;
                s10 += qb * ka;  s11 += qb * kb;  s12 += qb * kc2;  s13 += qb * kd;
            }
            float sva[4] = {s00, s01, s02, s03};
            float svb[4] = {s10, s11, s12, s13};
            #pragma unroll
            for (int m = 0; m < 4; m++) {
                int j  = tx + 16 * m;
                int gi = __ldg(idxg + ci * KC + j);
                float a = sva[m] * ATTN_SCALE;
                float b = svb[m] * ATTN_SCALE;
                if (gi < 0) { a = NEG_INF; b = NEG_INF; }
                sm[PS_OFF + ty * PSTRIDE + j]        = a;
                sm[PS_OFF + (ty + 16) * PSTRIDE + j] = b;
            }
        }
        __syncthreads();

        // ---- online softmax row update (one thread per head) ----
        if (tid < HG) {
            const int h = tid;
            float* prow = &sm[PS_OFF + h * PSTRIDE];
            float mc = NEG_INF;
            #pragma unroll 8
            for (int j = 0; j < KC; j++) mc = fmaxf(mc, prow[j]);
            float mp = sm[MS_OFF + h];
            float mn = fmaxf(mp, mc);
            float corr = (mp == NEG_INF) ? 0.f : __expf(mp - mn);
            float ssum = 0.f;
            #pragma unroll 8
            for (int j = 0; j < KC; j++) {
                float v = prow[j];
                float p = (v == NEG_INF) ? 0.f : __expf(v - mn);
                prow[j] = p;
                ssum += p;
            }
            sm[LS_OFF + h] = sm[LS_OFF + h] * corr + ssum;
            sm[MS_OFF + h] = mn;
            sm[CS_OFF + h] = corr;
        }
        __syncthreads();

        // ---- PV: acc = acc*corr + P_chunk @ V_chunk ----
        {
            float cr[4];
            #pragma unroll
            for (int i = 0; i < 4; i++) cr[i] = sm[CS_OFF + w + 8 * i];
            #pragma unroll
            for (int i = 0; i < 4; i++)
                #pragma unroll
                for (int k2 = 0; k2 < 16; k2++)
                    acc[i][k2] *= cr[i];

            #pragma unroll 2
            for (int j = 0; j < KC; j++) {
                float p0 = sm[PS_OFF + (w     ) * PSTRIDE + j];
                float p1 = sm[PS_OFF + (w +  8) * PSTRIDE + j];
                float p2 = sm[PS_OFF + (w + 16) * PSTRIDE + j];
                float p3 = sm[PS_OFF + (w + 24) * PSTRIDE + j];
                const float* vr = &sm[KS_OFF + j * KSTRIDE + c];
                #pragma unroll
                for (int k2 = 0; k2 < 16; k2++) {
                    float vv = vr[32 * k2];
                    acc[0][k2] += p0 * vv;
                    acc[1][k2] += p1 * vv;
                    acc[2][k2] += p2 * vv;
                    acc[3][k2] += p3 * vv;
                }
            }
        }
    }

    // ---- finalize: fold in sink, normalize, write out ----
    #pragma unroll
    for (int i = 0; i < 4; i++) {
        int h  = w + 8 * i;
        int gh = hblk + h;
        float m  = sm[MS_OFF + h];
        float l  = sm[LS_OFF + h];
        float sk = __ldg(sink + gh);
        float M  = fmaxf(m, sk);
        float cf = (m == NEG_INF) ? 0.f : __expf(m - M);
        float denom = l * cf + __expf(sk - M);
        float scl = cf / denom;
        float* og = out + ((size_t)t * NHEADS + gh) * DVDIM;
        #pragma unroll
        for (int k2 = 0; k2 < 16; k2++)
            og[c + 32 * k2] = acc[i][k2] * scl;
    }
}

extern "C" void kernel_launch(void* const* d_in, const int* in_sizes, int n_in,
                              void* d_out, int out_size)
{
    const float* q    = (const float*)d_in[0];
    const float* kv   = (const float*)d_in[1];
    const int*   topk = (const int*)d_in[2];
    const float* sink = (const float*)d_in[3];
    float* out = (float*)d_out;

    const size_t smem_bytes = SM_TOTAL * sizeof(float);  // 230528
    cudaFuncSetAttribute(mla_sparse_attn_kernel,
                         cudaFuncAttributeMaxDynamicSharedMemorySize,
                         (int)smem_bytes);
    dim3 grid(NHEADS / HG, T_TOK);
    mla_sparse_attn_kernel<<<grid, NTHREADS, smem_bytes>>>(q, kv, topk, sink, out);
}

// round 3
// speedup vs baseline: 1.0488x; 1.0004x over previous
#include <cuda_runtime.h>
#include <math_constants.h>

#define T_TOK    512
#define NHEADS   64
#define DQK      576
#define DVDIM    512
#define TOPKN    512
#define HG       32
#define KC       64
#define KSTRIDE  577   // 577 % 32 == 1 -> conflict-free row access
#define PSTRIDE  67    // 67 % 32 == 3  -> conflict-free column access
#define NTHREADS 256
#define ATTN_SCALE 0.04166666666666666f  // 576^-0.5 == 1/24

// shared memory layout (float offsets)
#define QS_OFF 0
#define QS_SZ  (HG * KSTRIDE)               // 18464
#define KS_OFF (QS_OFF + QS_SZ)
#define KS_SZ  (KC * KSTRIDE)               // 36928
#define PS_OFF (KS_OFF + KS_SZ)
#define PS_SZ  (HG * PSTRIDE)               // 2144
#define MS_OFF (PS_OFF + PS_SZ)
#define LS_OFF (MS_OFF + HG)
#define CS_OFF (LS_OFF + HG)
#define SM_TOTAL (CS_OFF + HG)              // 57632 floats = 230528 bytes

__global__ __launch_bounds__(NTHREADS, 1)
void mla_sparse_attn_kernel(const float* __restrict__ q,
                            const float* __restrict__ kv,
                            const int*   __restrict__ topk,
                            const float* __restrict__ sink,
                            float*       __restrict__ out)
{
    extern __shared__ float sm[];
    const int tid  = threadIdx.x;
    const int t    = blockIdx.y;
    const int hblk = blockIdx.x * HG;

    const float NEG_INF = -CUDART_INF_F;

    // ---- load Q tile (HG x 576) into smem ----
    {
        const float* qg = q + ((size_t)t * NHEADS + hblk) * DQK;
        for (int i = tid; i < HG * (DQK / 4); i += NTHREADS) {
            int row = i / (DQK / 4);
            int c4  = i % (DQK / 4);
            float4 v = *reinterpret_cast<const float4*>(qg + (size_t)row * DQK + c4 * 4);
            float* dst = &sm[QS_OFF + row * KSTRIDE + c4 * 4];
            dst[0] = v.x; dst[1] = v.y; dst[2] = v.z; dst[3] = v.w;
        }
    }
    if (tid < HG) {
        sm[MS_OFF + tid] = NEG_INF;
        sm[LS_OFF + tid] = 0.f;
    }

    // PV mapping: warp w owns heads {w, w+8, w+16, w+24}; lane c owns dv = c + 32*k
    const int w = tid >> 5;
    const int c = tid & 31;
    float acc[4][16];
    #pragma unroll
    for (int i = 0; i < 4; i++)
        #pragma unroll
        for (int k2 = 0; k2 < 16; k2++)
            acc[i][k2] = 0.f;

    const int* idxg = topk + (size_t)t * TOPKN;

    for (int ci = 0; ci < TOPKN / KC; ci++) {
        __syncthreads();  // previous PV done before k_s/p_s overwrite; also covers init

        // ---- gather K chunk (64 rows x 576) into smem ----
        for (int i = tid; i < KC * (DQK / 4); i += NTHREADS) {
            int row = i / (DQK / 4);
            int c4  = i % (DQK / 4);
            int gi  = __ldg(idxg + ci * KC + row);
            float4 v;
            if (gi >= 0)
                v = *reinterpret_cast<const float4*>(kv + (size_t)gi * DQK + c4 * 4);
            else
                v = make_float4(0.f, 0.f, 0.f, 0.f);
            float* dst = &sm[KS_OFF + row * KSTRIDE + c4 * 4];
            dst[0] = v.x; dst[1] = v.y; dst[2] = v.z; dst[3] = v.w;
        }
        __syncthreads();

        // ---- QK: scores S[32][64], 2h x 4j register tile per thread ----
        {
            const int ty = tid >> 4, tx = tid & 15;
            const float* q0 = &sm[QS_OFF + ty * KSTRIDE];
            const float* q1 = &sm[QS_OFF + (ty + 16) * KSTRIDE];
            const float* k0 = &sm[KS_OFF + tx * KSTRIDE];
            const float* k1 = &sm[KS_OFF + (tx + 16) * KSTRIDE];
            const float* k2p = &sm[KS_OFF + (tx + 32) * KSTRIDE];
            const float* k3 = &sm[KS_OFF + (tx + 48) * KSTRIDE];
            float s00 = 0.f, s01 = 0.f, s02 = 0.f, s03 = 0.f;
            float s10 = 0.f, s11 = 0.f, s12 = 0.f, s13 = 0.f;
            #pragma unroll 4
            for (int d = 0; d < DQK; d++) {
                float qa = q0[d], qb = q1[d];
                float ka = k0[d], kb = k1[d], kc2 = k2p[d], kd = k3[d];
                s00 += qa * ka;  s01 += qa * kb;  s02 += qa * kc2;  s03 += qa * kd;
                s10 += qb * ka;  s11 += qb * kb;  s12 += qb * kc2;  s13 += qb * kd;
            }
            float sva[4] = {s00, s01, s02, s03};
            float svb[4] = {s10, s11, s12, s13};
            #pragma unroll
            for (int m = 0; m < 4; m++) {
                int j  = tx + 16 * m;
                int gi = __ldg(idxg + ci * KC + j);
                float a = sva[m] * ATTN_SCALE;
                float b = svb[m] * ATTN_SCALE;
                if (gi < 0) { a = NEG_INF; b = NEG_INF; }
                sm[PS_OFF + ty * PSTRIDE + j]        = a;
                sm[PS_OFF + (ty + 16) * PSTRIDE + j] = b;
            }
        }
        __syncthreads();

        // ---- online softmax row update (one thread per head) ----
        if (tid < HG) {
            const int h = tid;
            float* prow = &sm[PS_OFF + h * PSTRIDE];
            float mc = NEG_INF;
            #pragma unroll 8
            for (int j = 0; j < KC; j++) mc = fmaxf(mc, prow[j]);
            float mp = sm[MS_OFF + h];
            float mn = fmaxf(mp, mc);
            float corr = (mp == NEG_INF) ? 0.f : __expf(mp - mn);
            float ssum = 0.f;
            #pragma unroll 8
            for (int j = 0; j < KC; j++) {
                float v = prow[j];
                float p = (v == NEG_INF) ? 0.f : __expf(v - mn);
                prow[j] = p;
                ssum += p;
            }
            sm[LS_OFF + h] = sm[LS_OFF + h] * corr + ssum;
            sm[MS_OFF + h] = mn;
            sm[CS_OFF + h] = corr;
        }
        __syncthreads();

        // ---- PV: acc = acc*corr + P_chunk @ V_chunk ----
        {
            float cr[4];
            #pragma unroll
            for (int i = 0; i < 4; i++) cr[i] = sm[CS_OFF + w + 8 * i];
            #pragma unroll
            for (int i = 0; i < 4; i++)
                #pragma unroll
                for (int k2 = 0; k2 < 16; k2++)
                    acc[i][k2] *= cr[i];

            #pragma unroll 2
            for (int j = 0; j < KC; j++) {
                float p0 = sm[PS_OFF + (w     ) * PSTRIDE + j];
                float p1 = sm[PS_OFF + (w +  8) * PSTRIDE + j];
                float p2 = sm[PS_OFF + (w + 16) * PSTRIDE + j];
                float p3 = sm[PS_OFF + (w + 24) * PSTRIDE + j];
                const float* vr = &sm[KS_OFF + j * KSTRIDE + c];
                #pragma unroll
                for (int k2 = 0; k2 < 16; k2++) {
                    float vv = vr[32 * k2];
                    acc[0][k2] += p0 * vv;
                    acc[1][k2] += p1 * vv;
                    acc[2][k2] += p2 * vv;
                    acc[3][k2] += p3 * vv;
                }
            }
        }
    }

    // ---- finalize: fold in sink, normalize, write out ----
    #pragma unroll
    for (int i = 0; i < 4; i++) {
        int h  = w + 8 * i;
        int gh = hblk + h;
        float m  = sm[MS_OFF + h];
        float l  = sm[LS_OFF + h];
        float sk = __ldg(sink + gh);
        float M  = fmaxf(m, sk);
        float cf = (m == NEG_INF) ? 0.f : __expf(m - M);
        float denom = l * cf + __expf(sk - M);
        float scl = cf / denom;
        float* og = out + ((size_t)t * NHEADS + gh) * DVDIM;
        #pragma unroll
        for (int k2 = 0; k2 < 16; k2++)
            og[c + 32 * k2] = acc[i][k2] * scl;
    }
}

extern "C" void kernel_launch(void* const* d_in, const int* in_sizes, int n_in,
                              void* d_out, int out_size)
{
    const float* q    = (const float*)d_in[0];
    const float* kv   = (const float*)d_in[1];
    const int*   topk = (const int*)d_in[2];
    const float* sink = (const float*)d_in[3];
    float* out = (float*)d_out;

    const size_t smem_bytes = SM_TOTAL * sizeof(float);  // 230528
    cudaFuncSetAttribute(mla_sparse_attn_kernel,
                         cudaFuncAttributeMaxDynamicSharedMemorySize,
                         (int)smem_bytes);
    dim3 grid(NHEADS / HG, T_TOK);
    mla_sparse_attn_kernel<<<grid, NTHREADS, smem_bytes>>>(q, kv, topk, sink, out);
}

// round 4
// speedup vs baseline: 1.0494x; 1.0006x over previous
#include <cuda_runtime.h>
#include <math_constants.h>

#define T_TOK    512
#define NHEADS   64
#define DQK      576
#define DVDIM    512
#define TOPKN    512
#define HG       32
#define KC       64
#define KSTRIDE  577   // 577 % 32 == 1 -> conflict-free row access
#define PSTRIDE  67    // 67 % 32 == 3  -> conflict-free column access
#define NTHREADS 256
#define ATTN_SCALE 0.04166666666666666f  // 576^-0.5 == 1/24

// shared memory layout (float offsets)
#define QS_OFF 0
#define QS_SZ  (HG * KSTRIDE)               // 18464
#define KS_OFF (QS_OFF + QS_SZ)
#define KS_SZ  (KC * KSTRIDE)               // 36928
#define PS_OFF (KS_OFF + KS_SZ)
#define PS_SZ  (HG * PSTRIDE)               // 2144
#define MS_OFF (PS_OFF + PS_SZ)
#define LS_OFF (MS_OFF + HG)
#define CS_OFF (LS_OFF + HG)
#define SM_TOTAL (CS_OFF + HG)              // 57632 floats = 230528 bytes

__global__ __launch_bounds__(NTHREADS, 1)
void mla_sparse_attn_kernel(const float* __restrict__ q,
                            const float* __restrict__ kv,
                            const int*   __restrict__ topk,
                            const float* __restrict__ sink,
                            float*       __restrict__ out)
{
    extern __shared__ float sm[];
    const int tid  = threadIdx.x;
    const int t    = blockIdx.y;
    const int hblk = blockIdx.x * HG;

    const float NEG_INF = -CUDART_INF_F;

    // ---- load Q tile (HG x 576) into smem ----
    {
        const float* qg = q + ((size_t)t * NHEADS + hblk) * DQK;
        for (int i = tid; i < HG * (DQK / 4); i += NTHREADS) {
            int row = i / (DQK / 4);
            int c4  = i % (DQK / 4);
            float4 v = *reinterpret_cast<const float4*>(qg + (size_t)row * DQK + c4 * 4);
            float* dst = &sm[QS_OFF + row * KSTRIDE + c4 * 4];
            dst[0] = v.x; dst[1] = v.y; dst[2] = v.z; dst[3] = v.w;
        }
    }
    if (tid < HG) {
        sm[MS_OFF + tid] = NEG_INF;
        sm[LS_OFF + tid] = 0.f;
    }

    // PV mapping: warp w owns heads {w, w+8, w+16, w+24}; lane c owns dv = c + 32*k
    const int w = tid >> 5;
    const int c = tid & 31;
    float acc[4][16];
    #pragma unroll
    for (int i = 0; i < 4; i++)
        #pragma unroll
        for (int k2 = 0; k2 < 16; k2++)
            acc[i][k2] = 0.f;

    const int* idxg = topk + (size_t)t * TOPKN;

    for (int ci = 0; ci < TOPKN / KC; ci++) {
        __syncthreads();  // previous PV done before k_s/p_s overwrite; also covers init

        // ---- gather K chunk (64 rows x 576) into smem ----
        for (int i = tid; i < KC * (DQK / 4); i += NTHREADS) {
            int row = i / (DQK / 4);
            int c4  = i % (DQK / 4);
            int gi  = __ldg(idxg + ci * KC + row);
            float4 v;
            if (gi >= 0)
                v = *reinterpret_cast<const float4*>(kv + (size_t)gi * DQK + c4 * 4);
            else
                v = make_float4(0.f, 0.f, 0.f, 0.f);
            float* dst = &sm[KS_OFF + row * KSTRIDE + c4 * 4];
            dst[0] = v.x; dst[1] = v.y; dst[2] = v.z; dst[3] = v.w;
        }
        __syncthreads();

        // ---- QK: scores S[32][64], 2h x 4j register tile per thread ----
        {
            const int ty = tid >> 4, tx = tid & 15;
            const float* q0 = &sm[QS_OFF + ty * KSTRIDE];
            const float* q1 = &sm[QS_OFF + (ty + 16) * KSTRIDE];
            const float* k0 = &sm[KS_OFF + tx * KSTRIDE];
            const float* k1 = &sm[KS_OFF + (tx + 16) * KSTRIDE];
            const float* k2p = &sm[KS_OFF + (tx + 32) * KSTRIDE];
            const float* k3 = &sm[KS_OFF + (tx + 48) * KSTRIDE];
            float s00 = 0.f, s01 = 0.f, s02 = 0.f, s03 = 0.f;
            float s10 = 0.f, s11 = 0.f, s12 = 0.f, s13 = 0.f;
            #pragma unroll 4
            for (int d = 0; d < DQK; d++) {
                float qa = q0[d], qb = q1[d];
                float ka = k0[d], kb = k1[d], kc2 = k2p[d], kd = k3[d];
                s00 += qa * ka;  s01 += qa * kb;  s02 += qa * kc2;  s03 += qa * kd;
                s10 += qb * ka;  s11 += qb * kb;  s12 += qb * kc2;  s13 += qb * kd;
            }
            float sva[4] = {s00, s01, s02, s03};
            float svb[4] = {s10, s11, s12, s13};
            #pragma unroll
            for (int m = 0; m < 4; m++) {
                int j  = tx + 16 * m;
                int gi = __ldg(idxg + ci * KC + j);
                float a = sva[m] * ATTN_SCALE;
                float b = svb[m] * ATTN_SCALE;
                if (gi < 0) { a = NEG_INF; b = NEG_INF; }
                sm[PS_OFF + ty * PSTRIDE + j]        = a;
                sm[PS_OFF + (ty + 16) * PSTRIDE + j] = b;
            }
        }
        __syncthreads();

        // ---- online softmax row update (one thread per head) ----
        if (tid < HG) {
            const int h = tid;
            float* prow = &sm[PS_OFF + h * PSTRIDE];
            float mc = NEG_INF;
            #pragma unroll 8
            for (int j = 0; j < KC; j++) mc = fmaxf(mc, prow[j]);
            float mp = sm[MS_OFF + h];
            float mn = fmaxf(mp, mc);
            float corr = (mp == NEG_INF) ? 0.f : __expf(mp - mn);
            float ssum = 0.f;
            #pragma unroll 8
            for (int j = 0; j < KC; j++) {
                float v = prow[j];
                float p = (v == NEG_INF) ? 0.f : __expf(v - mn);
                prow[j] = p;
                ssum += p;
            }
            sm[LS_OFF + h] = sm[LS_OFF + h] * corr + ssum;
            sm[MS_OFF + h] = mn;
            sm[CS_OFF + h] = corr;
        }
        __syncthreads();

        // ---- PV: acc = acc*corr + P_chunk @ V_chunk ----
        {
            float cr[4];
            #pragma unroll
            for (int i = 0; i < 4; i++) cr[i] = sm[CS_OFF + w + 8 * i];
            #pragma unroll
            for (int i = 0; i < 4; i++)
                #pragma unroll
                for (int k2 = 0; k2 < 16; k2++)
                    acc[i][k2] *= cr[i];

            #pragma unroll 2
            for (int j = 0; j < KC; j++) {
                float p0 = sm[PS_OFF + (w     ) * PSTRIDE + j];
                float p1 = sm[PS_OFF + (w +  8) * PSTRIDE + j];
                float p2 = sm[PS_OFF + (w + 16) * PSTRIDE + j];
                float p3 = sm[PS_OFF + (w + 24) * PSTRIDE + j];
                const float* vr = &sm[KS_OFF + j * KSTRIDE + c];
                #pragma unroll
                for (int k2 = 0; k2 < 16; k2++) {
                    float vv = vr[32 * k2];
                    acc[0][k2] += p0 * vv;
                    acc[1][k2] += p1 * vv;
                    acc[2][k2] += p2 * vv;
                    acc[3][k2] += p3 * vv;
                }
            }
        }
    }

    // ---- finalize: fold in sink, normalize, write out ----
    #pragma unroll
    for (int i = 0; i < 4; i++) {
        int h  = w + 8 * i;
        int gh = hblk + h;
        float m  = sm[MS_OFF + h];
        float l  = sm[LS_OFF + h];
        float sk = __ldg(sink + gh);
        float M  = fmaxf(m, sk);
        float cf = (m == NEG_INF) ? 0.f : __expf(m - M);
        float denom = l * cf + __expf(sk - M);
        float scl = cf / denom;
        float* og = out + ((size_t)t * NHEADS + gh) * DVDIM;
        #pragma unroll
        for (int k2 = 0; k2 < 16; k2++)
            og[c + 32 * k2] = acc[i][k2] * scl;
    }
}

extern "C" void kernel_launch(void* const* d_in, const int* in_sizes, int n_in,
                              void* d_out, int out_size)
{
    const float* q    = (const float*)d_in[0];
    const float* kv   = (const float*)d_in[1];
    const int*   topk = (const int*)d_in[2];
    const float* sink = (const float*)d_in[3];
    float* out = (float*)d_out;

    const size_t smem_bytes = SM_TOTAL * sizeof(float);  // 230528
    cudaFuncSetAttribute(mla_sparse_attn_kernel,
                         cudaFuncAttributeMaxDynamicSharedMemorySize,
                         (int)smem_bytes);
    dim3 grid(NHEADS / HG, T_TOK);
    mla_sparse_attn_kernel<<<grid, NTHREADS, smem_bytes>>>(q, kv, topk, sink, out);
}

// round 6
// speedup vs baseline: 3.2514x; 3.0982x over previous
#include <cuda_runtime.h>
#include <cstdint>

#define NTHR   512
#define HEADS  64
#define DDIM   576
#define TOPKN  512
#define KCH    128
#define SCALE_F 0.041666666666666664f
#define NEGINF __int_as_float(0xff800000)

// ---- smem byte offsets ----
#define OFF_IDX   0        // 512 * 4
#define OFF_M     2048     // 64 * 4
#define OFF_L     2304
#define OFF_C     2560
#define OFF_WMAX  2816     // 4 * 64 * 4
#define OFF_WSUM  3840
#define OFF_KSH   5120     // 128 rows * 144B
#define OFF_KSL   23552
#define OFF_QSH   41984    // 64 rows * 144B
#define OFF_QSL   51200    // ends 60416
#define OFF_VSH   5120     // 32 rows * 1040B (overlays K/Q region)
#define OFF_VSL   38400    // ends 71680
#define OFF_PH    71680    // 64 rows * 272B
#define OFF_PL    89088    // ends 106496
#define SMEM_TOTAL 106496

__device__ __forceinline__ uint32_t smem_u32(const void* p) {
    uint32_t a;
    asm("{ .reg .u64 t; cvta.to.shared.u64 t, %1; cvt.u32.u64 %0, t; }" : "=r"(a) : "l"(p));
    return a;
}
// fp32 pair -> packed bf16 hi (truncate) + bf16 lo (rounded residual)
__device__ __forceinline__ void split2(float x, float y, uint32_t& h2, uint32_t& l2) {
    uint32_t ux = __float_as_uint(x), uy = __float_as_uint(y);
    h2 = __byte_perm(ux, uy, 0x7632);
    float xl = x - __uint_as_float(ux & 0xffff0000u);
    float yl = y - __uint_as_float(uy & 0xffff0000u);
    asm("cvt.rn.bf16x2.f32 %0, %1, %2;" : "=r"(l2) : "f"(yl), "f"(xl));
}
__device__ __forceinline__ void ldsm4(uint32_t* r, uint32_t a) {
    asm volatile("ldmatrix.sync.aligned.m8n8.x4.shared.b16 {%0,%1,%2,%3}, [%4];"
                 : "=r"(r[0]), "=r"(r[1]), "=r"(r[2]), "=r"(r[3]) : "r"(a));
}
__device__ __forceinline__ void ldsm4t(uint32_t* r, uint32_t a) {
    asm volatile("ldmatrix.sync.aligned.m8n8.x4.trans.shared.b16 {%0,%1,%2,%3}, [%4];"
                 : "=r"(r[0]), "=r"(r[1]), "=r"(r[2]), "=r"(r[3]) : "r"(a));
}
__device__ __forceinline__ void mma16(float* d, const uint32_t* a, uint32_t b0, uint32_t b1) {
    asm volatile(
        "mma.sync.aligned.m16n8k16.row.col.f32.bf16.bf16.f32 "
        "{%0,%1,%2,%3}, {%4,%5,%6,%7}, {%8,%9}, {%0,%1,%2,%3};"
        : "+f"(d[0]), "+f"(d[1]), "+f"(d[2]), "+f"(d[3])
        : "r"(a[0]), "r"(a[1]), "r"(a[2]), "r"(a[3]), "r"(b0), "r"(b1));
}

__global__ __launch_bounds__(NTHR, 1)
void mla_mma_kernel(const float* __restrict__ q,
                    const float* __restrict__ kv,
                    const int*   __restrict__ topk,
                    const float* __restrict__ sink,
                    float*       __restrict__ out)
{
    extern __shared__ char sm[];
    const uint32_t smb = smem_u32(sm);
    const int tid = threadIdx.x;
    const int w = tid >> 5, l = tid & 31;
    const int hg = w >> 2;          // head group (16 heads)
    const int kg = w & 3;           // QK: key subgroup of 32; PV: dv group of 128
    const int t = blockIdx.x;

    int*   idx_s  = reinterpret_cast<int*>(sm + OFF_IDX);
    float* m_s    = reinterpret_cast<float*>(sm + OFF_M);
    float* l_s    = reinterpret_cast<float*>(sm + OFF_L);
    float* c_s    = reinterpret_cast<float*>(sm + OFF_C);
    float* wmax_s = reinterpret_cast<float*>(sm + OFF_WMAX);
    float* wsum_s = reinterpret_cast<float*>(sm + OFF_WSUM);

    idx_s[tid] = __ldg(topk + (size_t)t * TOPKN + tid);
    if (tid < HEADS) { m_s[tid] = __ldg(sink + tid); l_s[tid] = 1.f; }

    float o[16][4];
    #pragma unroll
    for (int i = 0; i < 16; ++i)
        #pragma unroll
        for (int j = 0; j < 4; ++j) o[i][j] = 0.f;

    for (int ci = 0; ci < 4; ++ci) {
        float sacc[4][4];
        #pragma unroll
        for (int i = 0; i < 4; ++i)
            #pragma unroll
            for (int j = 0; j < 4; ++j) sacc[i][j] = 0.f;

        // ============ QK over 9 d-slices of 64 ============
        for (int ds = 0; ds < 9; ++ds) {
            __syncthreads();   // prior smem reads done (also covers idx/m init)
            {   // gather K slice [128 keys x 64 d]
                int row = tid >> 2, qf = tid & 3;
                int gi = idx_s[ci * KCH + row];
                const float* src = kv + (size_t)gi * DDIM + ds * 64 + qf * 16;
                char* dh = sm + OFF_KSH + row * 144 + qf * 32;
                char* dl = sm + OFF_KSL + row * 144 + qf * 32;
                #pragma unroll
                for (int j = 0; j < 4; ++j) {
                    float4 v = make_float4(0.f, 0.f, 0.f, 0.f);
                    if (gi >= 0) v = *reinterpret_cast<const float4*>(src + j * 4);
                    uint32_t h0, l0, h1, l1;
                    split2(v.x, v.y, h0, l0); split2(v.z, v.w, h1, l1);
                    *reinterpret_cast<uint2*>(dh + j * 8) = make_uint2(h0, h1);
                    *reinterpret_cast<uint2*>(dl + j * 8) = make_uint2(l0, l1);
                }
            }
            {   // Q slice [64 heads x 64 d]
                int row = tid >> 3, qf = tid & 7;
                const float* src = q + ((size_t)t * HEADS + row) * DDIM + ds * 64 + qf * 8;
                char* dh = sm + OFF_QSH + row * 144 + qf * 16;
                char* dl = sm + OFF_QSL + row * 144 + qf * 16;
                #pragma unroll
                for (int j = 0; j < 2; ++j) {
                    float4 v = *reinterpret_cast<const float4*>(src + j * 4);
                    uint32_t h0, l0, h1, l1;
                    split2(v.x, v.y, h0, l0); split2(v.z, v.w, h1, l1);
                    *reinterpret_cast<uint2*>(dh + j * 8) = make_uint2(h0, h1);
                    *reinterpret_cast<uint2*>(dl + j * 8) = make_uint2(l0, l1);
                }
            }
            __syncthreads();
            #pragma unroll
            for (int ks = 0; ks < 4; ++ks) {
                uint32_t qh[4], ql[4], kh[8], kl[8];
                uint32_t qa = smb + OFF_QSH + (hg * 16 + (l & 15)) * 144 + (ks * 16 + (l >> 4) * 8) * 2;
                ldsm4(qh, qa);
                ldsm4(ql, qa + (OFF_QSL - OFF_QSH));
                uint32_t ka = smb + OFF_KSH + (kg * 32 + (l & 15)) * 144 + (ks * 16 + (l >> 4) * 8) * 2;
                ldsm4(kh, ka);
                ldsm4(kh + 4, ka + 16 * 144);
                ldsm4(kl, ka + (OFF_KSL - OFF_KSH));
                ldsm4(kl + 4, ka + (OFF_KSL - OFF_KSH) + 16 * 144);
                mma16(sacc[0], qh, kh[0], kh[2]); mma16(sacc[0], qh, kl[0], kl[2]); mma16(sacc[0], ql, kh[0], kh[2]);
                mma16(sacc[1], qh, kh[1], kh[3]); mma16(sacc[1], qh, kl[1], kl[3]); mma16(sacc[1], ql, kh[1], kh[3]);
                mma16(sacc[2], qh, kh[4], kh[6]); mma16(sacc[2], qh, kl[4], kl[6]); mma16(sacc[2], ql, kh[4], kh[6]);
                mma16(sacc[3], qh, kh[5], kh[7]); mma16(sacc[3], qh, kl[5], kl[7]); mma16(sacc[3], ql, kh[5], kh[7]);
            }
        }

        // ============ online softmax (register fragments) ============
        float rm0 = NEGINF, rm1 = NEGINF;
        #pragma unroll
        for (int nt = 0; nt < 4; ++nt) {
            int kb = ci * KCH + kg * 32 + nt * 8 + (l & 3) * 2;
            bool v0 = idx_s[kb] >= 0, v1 = idx_s[kb + 1] >= 0;
            float s0 = v0 ? sacc[nt][0] * SCALE_F : NEGINF;
            float s1 = v1 ? sacc[nt][1] * SCALE_F : NEGINF;
            float s2 = v0 ? sacc[nt][2] * SCALE_F : NEGINF;
            float s3 = v1 ? sacc[nt][3] * SCALE_F : NEGINF;
            sacc[nt][0] = s0; sacc[nt][1] = s1; sacc[nt][2] = s2; sacc[nt][3] = s3;
            rm0 = fmaxf(rm0, fmaxf(s0, s1));
            rm1 = fmaxf(rm1, fmaxf(s2, s3));
        }
        rm0 = fmaxf(rm0, __shfl_xor_sync(0xffffffffu, rm0, 1));
        rm0 = fmaxf(rm0, __shfl_xor_sync(0xffffffffu, rm0, 2));
        rm1 = fmaxf(rm1, __shfl_xor_sync(0xffffffffu, rm1, 1));
        rm1 = fmaxf(rm1, __shfl_xor_sync(0xffffffffu, rm1, 2));
        if ((l & 3) == 0) {
            wmax_s[kg * 64 + hg * 16 + (l >> 2)]     = rm0;
            wmax_s[kg * 64 + hg * 16 + 8 + (l >> 2)] = rm1;
        }
        __syncthreads();
        if (tid < HEADS) {
            float mo = m_s[tid];
            float mn = mo;
            #pragma unroll
            for (int g = 0; g < 4; ++g) mn = fmaxf(mn, wmax_s[g * 64 + tid]);
            float cr = __expf(mo - mn);
            m_s[tid] = mn; c_s[tid] = cr; l_s[tid] *= cr;
        }
        __syncthreads();
        float mr0 = m_s[hg * 16 + (l >> 2)];
        float mr1 = m_s[hg * 16 + 8 + (l >> 2)];
        float sum0 = 0.f, sum1 = 0.f;
        #pragma unroll
        for (int nt = 0; nt < 4; ++nt) {
            float e0 = __expf(sacc[nt][0] - mr0);
            float e1 = __expf(sacc[nt][1] - mr0);
            float e2 = __expf(sacc[nt][2] - mr1);
            float e3 = __expf(sacc[nt][3] - mr1);
            sum0 += e0 + e1; sum1 += e2 + e3;
            uint32_t ha, la, hb, lb;
            split2(e0, e1, ha, la);
            split2(e2, e3, hb, lb);
            uint32_t col = (uint32_t)(kg * 32 + nt * 8 + (l & 3) * 2) * 2;
            uint32_t r0o = (uint32_t)(hg * 16 + (l >> 2)) * 272 + col;
            uint32_t r1o = r0o + 8 * 272;
            *reinterpret_cast<uint32_t*>(sm + OFF_PH + r0o) = ha;
            *reinterpret_cast<uint32_t*>(sm + OFF_PL + r0o) = la;
            *reinterpret_cast<uint32_t*>(sm + OFF_PH + r1o) = hb;
            *reinterpret_cast<uint32_t*>(sm + OFF_PL + r1o) = lb;
        }
        sum0 += __shfl_xor_sync(0xffffffffu, sum0, 1);
        sum0 += __shfl_xor_sync(0xffffffffu, sum0, 2);
        sum1 += __shfl_xor_sync(0xffffffffu, sum1, 1);
        sum1 += __shfl_xor_sync(0xffffffffu, sum1, 2);
        if ((l & 3) == 0) {
            wsum_s[kg * 64 + hg * 16 + (l >> 2)]     = sum0;
            wsum_s[kg * 64 + hg * 16 + 8 + (l >> 2)] = sum1;
        }
        __syncthreads();
        if (tid < HEADS)
            l_s[tid] += wsum_s[tid] + wsum_s[64 + tid] + wsum_s[128 + tid] + wsum_s[192 + tid];
        float c0 = c_s[hg * 16 + (l >> 2)];
        float c1 = c_s[hg * 16 + 8 + (l >> 2)];
        #pragma unroll
        for (int nt = 0; nt < 16; ++nt) {
            o[nt][0] *= c0; o[nt][1] *= c0; o[nt][2] *= c1; o[nt][3] *= c1;
        }

        // ============ PV over 4 key-steps of 32 ============
        for (int kst = 0; kst < 4; ++kst) {
            __syncthreads();   // P writes visible / prior V reads done
            {   // gather V slice [32 keys x 512 dv]
                int row = tid >> 4, f4 = tid & 15;
                int gi = idx_s[ci * KCH + kst * 32 + row];
                const float* src = kv + (size_t)gi * DDIM;
                char* dh = sm + OFF_VSH + row * 1040;
                char* dl = sm + OFF_VSL + row * 1040;
                #pragma unroll
                for (int j = 0; j < 8; ++j) {
                    int dv = (f4 + 16 * j) * 4;
                    float4 v = make_float4(0.f, 0.f, 0.f, 0.f);
                    if (gi >= 0) v = *reinterpret_cast<const float4*>(src + dv);
                    uint32_t h0, l0, h1, l1;
                    split2(v.x, v.y, h0, l0); split2(v.z, v.w, h1, l1);
                    *reinterpret_cast<uint2*>(dh + dv * 2) = make_uint2(h0, h1);
                    *reinterpret_cast<uint2*>(dl + dv * 2) = make_uint2(l0, l1);
                }
            }
            __syncthreads();
            #pragma unroll
            for (int kk = 0; kk < 2; ++kk) {
                uint32_t ph[4], pl[4];
                uint32_t pa = smb + OFF_PH + (hg * 16 + (l & 15)) * 272 +
                              (kst * 32 + kk * 16 + (l >> 4) * 8) * 2;
                ldsm4(ph, pa);
                ldsm4(pl, pa + (OFF_PL - OFF_PH));
                #pragma unroll
                for (int dvt = 0; dvt < 8; ++dvt) {
                    uint32_t vh[4], vl[4];
                    uint32_t va = smb + OFF_VSH + (kk * 16 + (l & 15)) * 1040 +
                                  (kg * 128 + dvt * 16 + (l >> 4) * 8) * 2;
                    ldsm4t(vh, va);
                    ldsm4t(vl, va + (OFF_VSL - OFF_VSH));
                    float* o0 = o[dvt * 2];
                    float* o1 = o[dvt * 2 + 1];
                    mma16(o0, ph, vh[0], vh[1]); mma16(o0, ph, vl[0], vl[1]); mma16(o0, pl, vh[0], vh[1]);
                    mma16(o1, ph, vh[2], vh[3]); mma16(o1, ph, vl[2], vl[3]); mma16(o1, pl, vh[2], vh[3]);
                }
            }
        }
        __syncthreads();   // V reads done before next chunk's K gather
    }

    // ============ epilogue ============
    float n0 = 1.f / l_s[hg * 16 + (l >> 2)];
    float n1 = 1.f / l_s[hg * 16 + 8 + (l >> 2)];
    float* ob0 = out + ((size_t)t * HEADS + hg * 16 + (l >> 2)) * 512;
    float* ob1 = ob0 + 8 * 512;
    #pragma unroll
    for (int nt = 0; nt < 16; ++nt) {
        int dv = kg * 128 + nt * 8 + (l & 3) * 2;
        *reinterpret_cast<float2*>(ob0 + dv) = make_float2(o[nt][0] * n0, o[nt][1] * n0);
        *reinterpret_cast<float2*>(ob1 + dv) = make_float2(o[nt][2] * n1, o[nt][3] * n1);
    }
}

extern "C" void kernel_launch(void* const* d_in, const int* in_sizes, int n_in,
                              void* d_out, int out_size)
{
    const float* q    = (const float*)d_in[0];
    const float* kv   = (const float*)d_in[1];
    const int*   topk = (const int*)d_in[2];
    const float* sink = (const float*)d_in[3];
    float* out = (float*)d_out;

    cudaFuncSetAttribute(mla_mma_kernel, cudaFuncAttributeMaxDynamicSharedMemorySize, SMEM_TOTAL);
    mla_mma_kernel<<<512, NTHR, SMEM_TOTAL>>>(q, kv, topk, sink, out);
}

// round 7
// speedup vs baseline: 3.4859x; 1.0722x over previous
#include <cuda_runtime.h>
#include <cstdint>

#define NTHR   512
#define HEADS  64
#define DDIM   576
#define TOPKN  512
#define KCH    128
#define SCALE_F 0.041666666666666664f
#define NEGINF __int_as_float(0xff800000)

#define N4 4718592   // (32768*576)/4 == (512*64*576)/4

__device__ __align__(16) uint2 g_kvh[N4];
__device__ __align__(16) uint2 g_kvl[N4];
__device__ __align__(16) uint2 g_qh[N4];
__device__ __align__(16) uint2 g_ql[N4];

// ---- smem byte offsets ----
#define OFF_IDX   0
#define OFF_M     2048
#define OFF_L     2304
#define OFF_C     2560
#define OFF_WMAX  2816
#define OFF_WSUM  3840
#define KH_(i)    (5120 + (i)*36864)     // K slice: 128 rows * 144B, hi; lo at +18432
#define QH_(i)    (78848 + (i)*18432)    // Q slice: 64 rows * 144B, hi; lo at +9216
#define VH_(i)    (5120 + (i)*66560)     // V tile: 32 rows * 1040B, hi; lo at +33280
#define OFF_PH    138240                 // P: 64 rows * 272B; lo at +17408
#define OFF_PL    155648
#define SMEM_TOTAL 173056

__device__ __forceinline__ uint32_t smem_u32(const void* p) {
    uint32_t a;
    asm("{ .reg .u64 t; cvta.to.shared.u64 t, %1; cvt.u32.u64 %0, t; }" : "=r"(a) : "l"(p));
    return a;
}
__device__ __forceinline__ void split2(float x, float y, uint32_t& h2, uint32_t& l2) {
    uint32_t ux = __float_as_uint(x), uy = __float_as_uint(y);
    h2 = __byte_perm(ux, uy, 0x7632);
    float xl = x - __uint_as_float(ux & 0xffff0000u);
    float yl = y - __uint_as_float(uy & 0xffff0000u);
    asm("cvt.rn.bf16x2.f32 %0, %1, %2;" : "=r"(l2) : "f"(yl), "f"(xl));
}
__device__ __forceinline__ void ldsm4(uint32_t* r, uint32_t a) {
    asm volatile("ldmatrix.sync.aligned.m8n8.x4.shared.b16 {%0,%1,%2,%3}, [%4];"
                 : "=r"(r[0]), "=r"(r[1]), "=r"(r[2]), "=r"(r[3]) : "r"(a));
}
__device__ __forceinline__ void ldsm4t(uint32_t* r, uint32_t a) {
    asm volatile("ldmatrix.sync.aligned.m8n8.x4.trans.shared.b16 {%0,%1,%2,%3}, [%4];"
                 : "=r"(r[0]), "=r"(r[1]), "=r"(r[2]), "=r"(r[3]) : "r"(a));
}
__device__ __forceinline__ void mma16(float* d, const uint32_t* a, uint32_t b0, uint32_t b1) {
    asm volatile(
        "mma.sync.aligned.m16n8k16.row.col.f32.bf16.bf16.f32 "
        "{%0,%1,%2,%3}, {%4,%5,%6,%7}, {%8,%9}, {%0,%1,%2,%3};"
        : "+f"(d[0]), "+f"(d[1]), "+f"(d[2]), "+f"(d[3])
        : "r"(a[0]), "r"(a[1]), "r"(a[2]), "r"(a[3]), "r"(b0), "r"(b1));
}
__device__ __forceinline__ void cpa(uint32_t dst, const void* src, uint32_t sz) {
    asm volatile("cp.async.cg.shared.global [%0], [%1], 16, %2;"
                 :: "r"(dst), "l"(src), "r"(sz) : "memory");
}
#define CP_COMMIT() asm volatile("cp.async.commit_group;" ::: "memory")
#define CP_WAIT(n)  asm volatile("cp.async.wait_group %0;" :: "n"(n) : "memory")

// ================= preprocessing: fp32 -> bf16 hi/lo =================
__global__ __launch_bounds__(256)
void conv_kernel(const float* __restrict__ kv, const float* __restrict__ qq)
{
    uint32_t i = blockIdx.x * 256u + threadIdx.x;
    const float* src;
    uint2 *dh, *dl;
    uint32_t o;
    if (i < N4) {
        o = i; src = kv + (size_t)o * 4; dh = g_kvh; dl = g_kvl;
    } else {
        o = i - N4; src = qq + (size_t)o * 4; dh = g_qh; dl = g_ql;
    }
    float4 v = *reinterpret_cast<const float4*>(src);
    uint32_t h0, l0, h1, l1;
    split2(v.x, v.y, h0, l0);
    split2(v.z, v.w, h1, l1);
    dh[o] = make_uint2(h0, h1);
    dl[o] = make_uint2(l0, l1);
}

// ================= gather issue helpers =================
__device__ __forceinline__ void issue_kq(uint32_t smb, const int* idx_s,
                                         int ci, int ds, int t, int tid, int bi)
{
    {   // K slice [128 keys x 64 d]: 4 threads/row, 2 hi + 2 lo chunks each
        int row = tid >> 2, sub = tid & 3;
        int gi = idx_s[ci * KCH + row];
        uint32_t sz = gi >= 0 ? 16u : 0u;
        size_t rb = (size_t)(gi >= 0 ? gi : 0) * 1152 + (size_t)ds * 128 + sub * 32;
        const char* sh = (const char*)g_kvh + rb;
        const char* sl = (const char*)g_kvl + rb;
        uint32_t d = smb + KH_(bi) + row * 144 + sub * 32;
        cpa(d,              sh,      sz);
        cpa(d + 16,         sh + 16, sz);
        cpa(d + 18432,      sl,      sz);
        cpa(d + 18432 + 16, sl + 16, sz);
    }
    {   // Q slice [64 heads x 64 d]: 8 threads/row, 1 hi + 1 lo chunk each
        int row = tid >> 3, sub = tid & 7;
        size_t rb = ((size_t)t * 64 + row) * 1152 + (size_t)ds * 128 + sub * 16;
        uint32_t d = smb + QH_(bi) + row * 144 + sub * 16;
        cpa(d,        (const char*)g_qh + rb, 16);
        cpa(d + 9216, (const char*)g_ql + rb, 16);
    }
}
__device__ __forceinline__ void issue_v(uint32_t smb, const int* idx_s,
                                        int ci, int kst, int tid, int bi)
{
    // V tile [32 keys x 512 dv]: 16 threads/row, 4 hi + 4 lo chunks each
    int row = tid >> 4, sub = tid & 15;
    int gi = idx_s[ci * KCH + kst * 32 + row];
    uint32_t sz = gi >= 0 ? 16u : 0u;
    size_t rb = (size_t)(gi >= 0 ? gi : 0) * 1152 + sub * 64;
    const char* sh = (const char*)g_kvh + rb;
    const char* sl = (const char*)g_kvl + rb;
    uint32_t d = smb + VH_(bi) + row * 1040 + sub * 64;
    #pragma unroll
    for (int j = 0; j < 4; ++j) {
        cpa(d + j * 16,         sh + j * 16, sz);
        cpa(d + 33280 + j * 16, sl + j * 16, sz);
    }
}

// ================= main attention kernel =================
__global__ __launch_bounds__(NTHR, 1)
void mla_mma_kernel(const int* __restrict__ topk,
                    const float* __restrict__ sink,
                    float* __restrict__ out)
{
    extern __shared__ char sm[];
    const uint32_t smb = smem_u32(sm);
    const int tid = threadIdx.x;
    const int w = tid >> 5, l = tid & 31;
    const int hg = w >> 2;
    const int kg = w & 3;
    const int t = blockIdx.x;

    int*   idx_s  = reinterpret_cast<int*>(sm + OFF_IDX);
    float* m_s    = reinterpret_cast<float*>(sm + OFF_M);
    float* l_s    = reinterpret_cast<float*>(sm + OFF_L);
    float* c_s    = reinterpret_cast<float*>(sm + OFF_C);
    float* wmax_s = reinterpret_cast<float*>(sm + OFF_WMAX);
    float* wsum_s = reinterpret_cast<float*>(sm + OFF_WSUM);

    idx_s[tid] = __ldg(topk + (size_t)t * TOPKN + tid);
    if (tid < HEADS) { m_s[tid] = __ldg(sink + tid); l_s[tid] = 1.f; }
    __syncthreads();

    float o[16][4];
    #pragma unroll
    for (int i = 0; i < 16; ++i)
        #pragma unroll
        for (int j = 0; j < 4; ++j) o[i][j] = 0.f;

    for (int ci = 0; ci < 4; ++ci) {
        float sacc[4][4];
        #pragma unroll
        for (int i = 0; i < 4; ++i)
            #pragma unroll
            for (int j = 0; j < 4; ++j) sacc[i][j] = 0.f;

        // ============ QK over 9 d-slices, double-buffered cp.async ============
        issue_kq(smb, idx_s, ci, 0, t, tid, 0);
        CP_COMMIT();
        for (int ds = 0; ds < 9; ++ds) {
            if (ds < 8) {
                issue_kq(smb, idx_s, ci, ds + 1, t, tid, (ds + 1) & 1);
                CP_COMMIT();
                CP_WAIT(1);
            } else {
                CP_WAIT(0);
            }
            __syncthreads();
            const int bi = ds & 1;
            #pragma unroll
            for (int ks = 0; ks < 4; ++ks) {
                uint32_t qh[4], ql[4], kh[8], kl[8];
                uint32_t qa = smb + QH_(bi) + (hg * 16 + (l & 15)) * 144 + (ks * 16 + (l >> 4) * 8) * 2;
                ldsm4(qh, qa);
                ldsm4(ql, qa + 9216);
                uint32_t ka = smb + KH_(bi) + (kg * 32 + (l & 15)) * 144 + (ks * 16 + (l >> 4) * 8) * 2;
                ldsm4(kh, ka);
                ldsm4(kh + 4, ka + 16 * 144);
                ldsm4(kl, ka + 18432);
                ldsm4(kl + 4, ka + 18432 + 16 * 144);
                mma16(sacc[0], qh, kh[0], kh[2]); mma16(sacc[0], qh, kl[0], kl[2]); mma16(sacc[0], ql, kh[0], kh[2]);
                mma16(sacc[1], qh, kh[1], kh[3]); mma16(sacc[1], qh, kl[1], kl[3]); mma16(sacc[1], ql, kh[1], kh[3]);
                mma16(sacc[2], qh, kh[4], kh[6]); mma16(sacc[2], qh, kl[4], kl[6]); mma16(sacc[2], ql, kh[4], kh[6]);
                mma16(sacc[3], qh, kh[5], kh[7]); mma16(sacc[3], qh, kl[5], kl[7]); mma16(sacc[3], ql, kh[5], kh[7]);
            }
            __syncthreads();
        }

        // prefetch first two V tiles (independent of softmax)
        issue_v(smb, idx_s, ci, 0, tid, 0);
        CP_COMMIT();
        issue_v(smb, idx_s, ci, 1, tid, 1);
        CP_COMMIT();

        // ============ online softmax (register fragments) ============
        float rm0 = NEGINF, rm1 = NEGINF;
        #pragma unroll
        for (int nt = 0; nt < 4; ++nt) {
            int kb = ci * KCH + kg * 32 + nt * 8 + (l & 3) * 2;
            bool v0 = idx_s[kb] >= 0, v1 = idx_s[kb + 1] >= 0;
            float s0 = v0 ? sacc[nt][0] * SCALE_F : NEGINF;
            float s1 = v1 ? sacc[nt][1] * SCALE_F : NEGINF;
            float s2 = v0 ? sacc[nt][2] * SCALE_F : NEGINF;
            float s3 = v1 ? sacc[nt][3] * SCALE_F : NEGINF;
            sacc[nt][0] = s0; sacc[nt][1] = s1; sacc[nt][2] = s2; sacc[nt][3] = s3;
            rm0 = fmaxf(rm0, fmaxf(s0, s1));
            rm1 = fmaxf(rm1, fmaxf(s2, s3));
        }
        rm0 = fmaxf(rm0, __shfl_xor_sync(0xffffffffu, rm0, 1));
        rm0 = fmaxf(rm0, __shfl_xor_sync(0xffffffffu, rm0, 2));
        rm1 = fmaxf(rm1, __shfl_xor_sync(0xffffffffu, rm1, 1));
        rm1 = fmaxf(rm1, __shfl_xor_sync(0xffffffffu, rm1, 2));
        if ((l & 3) == 0) {
            wmax_s[kg * 64 + hg * 16 + (l >> 2)]     = rm0;
            wmax_s[kg * 64 + hg * 16 + 8 + (l >> 2)] = rm1;
        }
        __syncthreads();
        if (tid < HEADS) {
            float mo = m_s[tid];
            float mn = mo;
            #pragma unroll
            for (int g = 0; g < 4; ++g) mn = fmaxf(mn, wmax_s[g * 64 + tid]);
            float cr = __expf(mo - mn);
            m_s[tid] = mn; c_s[tid] = cr; l_s[tid] *= cr;
        }
        __syncthreads();
        float mr0 = m_s[hg * 16 + (l >> 2)];
        float mr1 = m_s[hg * 16 + 8 + (l >> 2)];
        float sum0 = 0.f, sum1 = 0.f;
        #pragma unroll
        for (int nt = 0; nt < 4; ++nt) {
            float e0 = __expf(sacc[nt][0] - mr0);
            float e1 = __expf(sacc[nt][1] - mr0);
            float e2 = __expf(sacc[nt][2] - mr1);
            float e3 = __expf(sacc[nt][3] - mr1);
            sum0 += e0 + e1; sum1 += e2 + e3;
            uint32_t ha, la, hb, lb;
            split2(e0, e1, ha, la);
            split2(e2, e3, hb, lb);
            uint32_t col = (uint32_t)(kg * 32 + nt * 8 + (l & 3) * 2) * 2;
            uint32_t r0o = (uint32_t)(hg * 16 + (l >> 2)) * 272 + col;
            uint32_t r1o = r0o + 8 * 272;
            *reinterpret_cast<uint32_t*>(sm + OFF_PH + r0o) = ha;
            *reinterpret_cast<uint32_t*>(sm + OFF_PL + r0o) = la;
            *reinterpret_cast<uint32_t*>(sm + OFF_PH + r1o) = hb;
            *reinterpret_cast<uint32_t*>(sm + OFF_PL + r1o) = lb;
        }
        sum0 += __shfl_xor_sync(0xffffffffu, sum0, 1);
        sum0 += __shfl_xor_sync(0xffffffffu, sum0, 2);
        sum1 += __shfl_xor_sync(0xffffffffu, sum1, 1);
        sum1 += __shfl_xor_sync(0xffffffffu, sum1, 2);
        if ((l & 3) == 0) {
            wsum_s[kg * 64 + hg * 16 + (l >> 2)]     = sum0;
            wsum_s[kg * 64 + hg * 16 + 8 + (l >> 2)] = sum1;
        }
        __syncthreads();
        if (tid < HEADS)
            l_s[tid] += wsum_s[tid] + wsum_s[64 + tid] + wsum_s[128 + tid] + wsum_s[192 + tid];
        float c0 = c_s[hg * 16 + (l >> 2)];
        float c1 = c_s[hg * 16 + 8 + (l >> 2)];
        #pragma unroll
        for (int nt = 0; nt < 16; ++nt) {
            o[nt][0] *= c0; o[nt][1] *= c0; o[nt][2] *= c1; o[nt][3] *= c1;
        }

        // ============ PV over 4 key-steps, double-buffered cp.async ============
        for (int kst = 0; kst < 4; ++kst) {
            if (kst < 3) CP_WAIT(1); else CP_WAIT(0);
            __syncthreads();
            const int bi = kst & 1;
            #pragma unroll
            for (int kk = 0; kk < 2; ++kk) {
                uint32_t ph[4], pl[4];
                uint32_t pa = smb + OFF_PH + (hg * 16 + (l & 15)) * 272 +
                              (kst * 32 + kk * 16 + (l >> 4) * 8) * 2;
                ldsm4(ph, pa);
                ldsm4(pl, pa + 17408);
                #pragma unroll
                for (int dvt = 0; dvt < 8; ++dvt) {
                    uint32_t vh[4], vl[4];
                    uint32_t va = smb + VH_(bi) + (kk * 16 + (l & 15)) * 1040 +
                                  (kg * 128 + dvt * 16 + (l >> 4) * 8) * 2;
                    ldsm4t(vh, va);
                    ldsm4t(vl, va + 33280);
                    float* o0 = o[dvt * 2];
                    float* o1 = o[dvt * 2 + 1];
                    mma16(o0, ph, vh[0], vh[1]); mma16(o0, ph, vl[0], vl[1]); mma16(o0, pl, vh[0], vh[1]);
                    mma16(o1, ph, vh[2], vh[3]); mma16(o1, ph, vl[2], vl[3]); mma16(o1, pl, vh[2], vh[3]);
                }
            }
            __syncthreads();
            if (kst + 2 <= 3) {
                issue_v(smb, idx_s, ci, kst + 2, tid, kst & 1);
                CP_COMMIT();
            }
        }
    }

    // ============ epilogue ============
    float n0 = 1.f / l_s[hg * 16 + (l >> 2)];
    float n1 = 1.f / l_s[hg * 16 + 8 + (l >> 2)];
    float* ob0 = out + ((size_t)t * HEADS + hg * 16 + (l >> 2)) * 512;
    float* ob1 = ob0 + 8 * 512;
    #pragma unroll
    for (int nt = 0; nt < 16; ++nt) {
        int dv = kg * 128 + nt * 8 + (l & 3) * 2;
        *reinterpret_cast<float2*>(ob0 + dv) = make_float2(o[nt][0] * n0, o[nt][1] * n0);
        *reinterpret_cast<float2*>(ob1 + dv) = make_float2(o[nt][2] * n1, o[nt][3] * n1);
    }
}

extern "C" void kernel_launch(void* const* d_in, const int* in_sizes, int n_in,
                              void* d_out, int out_size)
{
    const float* q    = (const float*)d_in[0];
    const float* kv   = (const float*)d_in[1];
    const int*   topk = (const int*)d_in[2];
    const float* sink = (const float*)d_in[3];
    float* out = (float*)d_out;

    conv_kernel<<<(2 * N4) / 256, 256>>>(kv, q);

    cudaFuncSetAttribute(mla_mma_kernel, cudaFuncAttributeMaxDynamicSharedMemorySize, SMEM_TOTAL);
    mla_mma_kernel<<<512, NTHR, SMEM_TOTAL>>>(topk, sink, out);
}